// round 4
// baseline (speedup 1.0000x reference)
#include <cuda_runtime.h>

typedef unsigned long long u64;

#define D_F 16
#define HID 16

// One constant image holding all weights/biases, duplicated as (w,w) f32x2
// payloads. Warp-uniform LDCU -> UR operands for FFMA2 (rt 2 instead of 3).
#define OFF_W1 0       // [d][c][h]      768 u64
#define OFF_W2 768     // [d][g][h]     4096 u64
#define OFF_W3 4864    // [d][g][o]      768 u64
#define OFF_B1 5632    //                256 u64
#define OFF_B2 5888    //                256 u64
#define OFF_B3 6144    //                 48 u64
#define CP_TOT 6192    // 49536 B < 64 KB constant bank

__constant__ u64 cP[CP_TOT];
__device__   u64 g_stage[CP_TOT];

// ---- f32x2 packed helpers ----
__device__ __forceinline__ u64 ffma2(u64 a, u64 b, u64 c) {
    u64 r;
    asm("fma.rn.f32x2 %0, %1, %2, %3;" : "=l"(r) : "l"(a), "l"(b), "l"(c));
    return r;
}
__device__ __forceinline__ u64 pack2f(float lo, float hi) {
    u64 r;
    asm("mov.b64 %0, {%1, %2};" : "=l"(r)
        : "r"(__float_as_uint(lo)), "r"(__float_as_uint(hi)));
    return r;
}
__device__ __forceinline__ u64 relu2(u64 v) {
    unsigned lo, hi;
    asm("mov.b64 {%0, %1}, %2;" : "=r"(lo), "=r"(hi) : "l"(v));
    float flo = fmaxf(__uint_as_float(lo), 0.0f);
    float fhi = fmaxf(__uint_as_float(hi), 0.0f);
    return pack2f(flo, fhi);
}
__device__ __forceinline__ float lo_of(u64 v) {
    unsigned lo, hi;
    asm("mov.b64 {%0, %1}, %2;" : "=r"(lo), "=r"(hi) : "l"(v));
    return __uint_as_float(lo);
}

// Build the duplicated/transposed constant image in a staging buffer.
__global__ void prep_kernel(const float* __restrict__ W1, const float* __restrict__ b1,
                            const float* __restrict__ W2, const float* __restrict__ b2,
                            const float* __restrict__ W3, const float* __restrict__ b3)
{
    int i = blockIdx.x * blockDim.x + threadIdx.x;
    if (i >= CP_TOT) return;
    float v;
    if (i < OFF_W2) {                       // W1: [d][c][h] <- [d][h][c]
        int j = i - OFF_W1, d = j / 48, r = j % 48, c = r / HID, h = r % HID;
        v = W1[d * 48 + h * 3 + c];
    } else if (i < OFF_W3) {                // W2: identity [d][g][h]
        v = W2[i - OFF_W2];
    } else if (i < OFF_B1) {                // W3: [d][g][o] <- [d][o][g]
        int j = i - OFF_W3, d = j / 48, r = j % 48, g = r / 3, o = r % 3;
        v = W3[d * 48 + o * HID + g];
    } else if (i < OFF_B2) {
        v = b1[i - OFF_B1];
    } else if (i < OFF_B3) {
        v = b2[i - OFF_B2];
    } else {
        v = b3[i - OFF_B3];
    }
    unsigned u = __float_as_uint(v);
    g_stage[i] = ((u64)u << 32) | (u64)u;   // (w, w)
}

__global__ __launch_bounds__(128, 4)
void fields_kernel(const float* __restrict__ x, float* __restrict__ out, int N)
{
    const int q    = blockIdx.x * blockDim.x + threadIdx.x;
    const int base = q * 4;                 // 4 points/thread = 2 f32x2 pairs

    if (base + 3 < N) {
        u64 xA[3], xB[3];
        #pragma unroll
        for (int c = 0; c < 3; c++) {
            ulonglong2 v = *reinterpret_cast<const ulonglong2*>(x + (size_t)c * N + base);
            xA[c] = v.x; xB[c] = v.y;       // LDG.128
        }

        #pragma unroll 1
        for (int d = 0; d < D_F; d++) {
            const u64* w1  = cP + OFF_W1 + d * 48;    // [c][h]
            const u64* w2  = cP + OFF_W2 + d * 256;   // [g][h]
            const u64* w3  = cP + OFF_W3 + d * 48;    // [g][o]
            const u64* b1d = cP + OFF_B1 + d * HID;
            const u64* b2d = cP + OFF_B2 + d * HID;
            const u64* b3d = cP + OFF_B3 + d * 3;

            // ---- layer 1: h1 = relu(W1 @ x + b1) ----
            u64 h1A[HID], h1B[HID];
            #pragma unroll
            for (int h = 0; h < HID; h++) {
                u64 bb = b1d[h];                      // LDCU.64 (uniform)
                h1A[h] = bb; h1B[h] = bb;
            }
            #pragma unroll
            for (int c = 0; c < 3; c++) {
                u64 xa = xA[c], xb = xB[c];
                #pragma unroll
                for (int h = 0; h < HID; h++) {
                    u64 w = w1[c * HID + h];          // uniform const -> UR
                    h1A[h] = ffma2(w, xa, h1A[h]);
                    h1B[h] = ffma2(w, xb, h1B[h]);
                }
            }
            #pragma unroll
            for (int h = 0; h < HID; h++) { h1A[h] = relu2(h1A[h]); h1B[h] = relu2(h1B[h]); }

            // ---- layers 2+3 fused ----
            u64 oA[3], oB[3];
            #pragma unroll
            for (int o = 0; o < 3; o++) {
                u64 t = b3d[o];
                oA[o] = t; oB[o] = t;
            }

            #pragma unroll
            for (int g = 0; g < HID; g++) {
                u64 a = b2d[g];                       // LDCU.64
                u64 b = a;
                #pragma unroll
                for (int h = 0; h < HID; h++) {
                    u64 w = w2[g * HID + h];          // uniform const -> UR
                    a = ffma2(w, h1A[h], a);
                    b = ffma2(w, h1B[h], b);
                }
                a = relu2(a); b = relu2(b);

                #pragma unroll
                for (int o = 0; o < 3; o++) {
                    u64 w = w3[g * 3 + o];
                    oA[o] = ffma2(w, a, oA[o]);
                    oB[o] = ffma2(w, b, oB[o]);
                }
            }

            #pragma unroll
            for (int o = 0; o < 3; o++) {
                *reinterpret_cast<ulonglong2*>(out + (size_t)(d * 3 + o) * N + base) =
                    make_ulonglong2(oA[o], oB[o]);    // STG.128
            }
        }
    } else {
        // scalar tail (unused when N % 4 == 0)
        for (int p = base; p < N && p >= 0; p++) {
            float xs[3];
            #pragma unroll
            for (int c = 0; c < 3; c++) xs[c] = x[(size_t)c * N + p];
            for (int d = 0; d < D_F; d++) {
                float h1[HID];
                for (int h = 0; h < HID; h++) {
                    float s = lo_of(cP[OFF_B1 + d * HID + h]);
                    for (int c = 0; c < 3; c++)
                        s += lo_of(cP[OFF_W1 + d * 48 + c * HID + h]) * xs[c];
                    h1[h] = fmaxf(s, 0.0f);
                }
                float o0 = lo_of(cP[OFF_B3 + d * 3 + 0]);
                float o1 = lo_of(cP[OFF_B3 + d * 3 + 1]);
                float o2 = lo_of(cP[OFF_B3 + d * 3 + 2]);
                for (int g = 0; g < HID; g++) {
                    float s = lo_of(cP[OFF_B2 + d * HID + g]);
                    for (int h = 0; h < HID; h++)
                        s += lo_of(cP[OFF_W2 + d * 256 + g * HID + h]) * h1[h];
                    s = fmaxf(s, 0.0f);
                    o0 += lo_of(cP[OFF_W3 + d * 48 + g * 3 + 0]) * s;
                    o1 += lo_of(cP[OFF_W3 + d * 48 + g * 3 + 1]) * s;
                    o2 += lo_of(cP[OFF_W3 + d * 48 + g * 3 + 2]) * s;
                }
                out[(size_t)(d * 3 + 0) * N + p] = o0;
                out[(size_t)(d * 3 + 1) * N + p] = o1;
                out[(size_t)(d * 3 + 2) * N + p] = o2;
            }
        }
    }
}

extern "C" void kernel_launch(void* const* d_in, const int* in_sizes, int n_in,
                              void* d_out, int out_size)
{
    const float* x  = (const float*)d_in[0];
    const float* W1 = (const float*)d_in[1];
    const float* b1 = (const float*)d_in[2];
    const float* W2 = (const float*)d_in[3];
    const float* b2 = (const float*)d_in[4];
    const float* W3 = (const float*)d_in[5];
    const float* b3 = (const float*)d_in[6];
    float* out = (float*)d_out;

    const int N = in_sizes[0] / 3;          // x is [1,3,N]

    // 1) Build duplicated/transposed weight image in staging (device global).
    prep_kernel<<<(CP_TOT + 255) / 256, 256>>>(W1, b1, W2, b2, W3, b3);

    // 2) Copy staging -> constant bank (async D2D memcpy; graph-capturable).
    void* stage_ptr = nullptr;
    cudaGetSymbolAddress(&stage_ptr, g_stage);
    cudaMemcpyToSymbolAsync(cP, stage_ptr, CP_TOT * sizeof(u64), 0,
                            cudaMemcpyDeviceToDevice, 0);

    // 3) Main kernel: weights from constant memory only.
    const int nq   = (N + 3) / 4;
    const int grid = (nq + 127) / 128;
    fields_kernel<<<grid, 128>>>(x, out, N);
}